// round 15
// baseline (speedup 1.0000x reference)
#include <cuda_runtime.h>
#include <cuda_fp16.h>
#include <cstdint>

// ---------------- problem constants ----------------
#define DD   1024
#define EE   8
#define HH   4096
#define OO   1024
#define NTOK 4096
#define NPAIR (NTOK * 2)
#define ROWS_CAP (NPAIR + EE * 128)   // 9216

// ---------------- GEMM tile config ----------------
#define BM 128
#define BN 128
#define BK 16        // K elems per stage (double-buffered)
#define RWA 20       // A smem pitch (u32): 16 data + 4 pad; frag loads conflict-free
#define RWB 136      // B smem pitch (u32): 136%32==8 -> frag loads conflict-free

// ---------------- asm helpers ----------------
__device__ __forceinline__ void mma_tf32(float* c, const uint32_t* a, const uint32_t* b) {
    asm volatile("mma.sync.aligned.m16n8k8.row.col.f32.tf32.tf32.f32 "
                 "{%0,%1,%2,%3}, {%4,%5,%6,%7}, {%8,%9}, {%0,%1,%2,%3};"
                 : "+f"(c[0]), "+f"(c[1]), "+f"(c[2]), "+f"(c[3])
                 : "r"(a[0]), "r"(a[1]), "r"(a[2]), "r"(a[3]), "r"(b[0]), "r"(b[1]));
}
__device__ __forceinline__ uint32_t f2tf32(float v) {
    uint32_t r;
    asm("cvt.rna.tf32.f32 %0, %1;" : "=r"(r) : "f"(v));
    return r;
}
__device__ __forceinline__ uint4 cvt4(float4 v) {
    uint4 o;
    o.x = f2tf32(v.x); o.y = f2tf32(v.y);
    o.z = f2tf32(v.z); o.w = f2tf32(v.w);
    return o;
}
__device__ __forceinline__ uint32_t f2h2(float lo, float hi) {
    __half2 h = __floats2half2_rn(lo, hi);
    return *(uint32_t*)&h;
}

// ---------------- scratch (static device globals; device-code access ONLY) ----------------
__device__ int   g_counts[EE];
__device__ int   g_cursor[EE];
__device__ int   g_off[EE + 1];
__device__ int   g_top_idx[NPAIR];
__device__ float g_top_w[NPAIR];
__device__ int   g_row_token[ROWS_CAP];
__device__ int   g_row_of_pair[NPAIR];
__device__ __align__(16) __half g_hf16[(size_t)ROWS_CAP * HH];   // hidden, fp16
__device__ __align__(16) float  g_y[(size_t)ROWS_CAP * OO];

// ---------------- small kernels ----------------
__global__ void router_kernel(const float* __restrict__ x,
                              const float* __restrict__ Wg,
                              const float* __restrict__ bg) {
    __shared__ float sWg[DD * EE];
    int tid = threadIdx.x;
    for (int i = tid * 4; i < DD * EE; i += blockDim.x * 4)
        *(float4*)&sWg[i] = *(const float4*)&Wg[i];
    __syncthreads();

    int warp = tid >> 5, lane = tid & 31;
    int n = blockIdx.x * 8 + warp;
    const float* xr = x + (size_t)n * DD;

    float acc[EE];
#pragma unroll
    for (int e = 0; e < EE; e++) acc[e] = 0.f;
    for (int d = lane; d < DD; d += 32) {
        float xv = xr[d];
#pragma unroll
        for (int e = 0; e < EE; e++) acc[e] += xv * sWg[d * EE + e];
    }
#pragma unroll
    for (int e = 0; e < EE; e++)
#pragma unroll
        for (int s = 16; s; s >>= 1) acc[e] += __shfl_xor_sync(0xffffffffu, acc[e], s);

    if (lane == 0) {
        float m = -1e30f;
#pragma unroll
        for (int e = 0; e < EE; e++) { acc[e] += bg[e]; m = fmaxf(m, acc[e]); }
        float s = 0.f;
#pragma unroll
        for (int e = 0; e < EE; e++) { acc[e] = __expf(acc[e] - m); s += acc[e]; }
        float inv = 1.f / s;
        int i0 = 0; float p0 = acc[0];
#pragma unroll
        for (int e = 1; e < EE; e++) if (acc[e] > p0) { p0 = acc[e]; i0 = e; }
        int i1 = -1; float p1 = -1.f;
#pragma unroll
        for (int e = 0; e < EE; e++) if (e != i0 && acc[e] > p1) { p1 = acc[e]; i1 = e; }

        g_top_idx[2 * n]     = i0; g_top_w[2 * n]     = p0 * inv;
        g_top_idx[2 * n + 1] = i1; g_top_w[2 * n + 1] = p1 * inv;
        atomicAdd(&g_counts[i0], 1);
        atomicAdd(&g_counts[i1], 1);
    }
}

__global__ void scan_kernel() {
    int off = 0;
    for (int e = 0; e < EE; e++) {
        g_off[e] = off;
        g_cursor[e] = off;
        off += (g_counts[e] + 127) & ~127;
    }
    g_off[EE] = off;
}

__global__ void scatter_kernel() {
    int p = blockIdx.x * blockDim.x + threadIdx.x;
    if (p >= NPAIR) return;
    int e = g_top_idx[p];
    int pos = atomicAdd(&g_cursor[e], 1);
    g_row_token[pos] = p >> 1;
    g_row_of_pair[p] = pos;
}

// ---------------- TF32 grouped GEMM: double-buffered, single sync/iter ----------------
// B (fp32 weights [E][K][N]) read raw, tf32-rounded at smem store, staged [k][n].
// A: GEMM1 = gathered fp32 x (tf32 cvt at store); GEMM2 = fp16 hidden (exact cvt).
// Loop: [prefetch LDG c+1] -> MMA(buf c&1) -> STS(buf 1-(c&1)) -> sync.
template <int KTOT, int NOUTT, bool G1>
__global__ __launch_bounds__(256, 1) void moe_gemm(const float* __restrict__ xArg,
                                                   const float* __restrict__ Barg,
                                                   const float* __restrict__ bias) {
    const int NOUT = NOUTT;

    __shared__ __align__(16) uint32_t sA[2][BM][RWA];   // [buf][m][k]
    __shared__ __align__(16) uint32_t sB[2][BK][RWB];   // [buf][k][n]
    __shared__ int stok[BM];

    const int tid = threadIdx.x;
    const int row0 = blockIdx.y * BM;
    if (row0 >= g_off[EE]) return;
    int e = 0;
#pragma unroll
    for (int i = 1; i < EE; i++) if (row0 >= g_off[i]) e = i;
    const int valid = g_off[e] + g_counts[e] - row0;
    const int n0 = blockIdx.x * BN;
    const float* __restrict__ Bbase = Barg + (size_t)e * KTOT * NOUT + n0;

    if (G1) {
        if (tid < BM) stok[tid] = (tid < valid) ? g_row_token[row0 + tid] : -1;
        __syncthreads();
    }

    // ---- loader slots (per K-stage of 16) ----
    // G1 A: 512 slots (128 rows x 4 float4); 2/thread
    const float* aF[2]; int adFo[2]; bool aok[2];
    // G2 A: 256 slots (128 rows x 2 eight-half chunks); 1/thread
    const __half* aH = nullptr; int adHo = 0;
    if (G1) {
#pragma unroll
        for (int j = 0; j < 2; j++) {
            int id = tid + 256 * j;
            int r = id >> 2, ch = id & 3;
            int tk = stok[r];
            aok[j] = (tk >= 0);
            long ar = aok[j] ? tk : 0;
            aF[j] = xArg + (size_t)ar * KTOT + ch * 4;
            adFo[j] = r * RWA + ch * 4;
        }
    } else {
        int r = tid >> 1, c8 = tid & 1;
        aH = g_hf16 + (size_t)(row0 + r) * KTOT + c8 * 8;
        adHo = r * RWA + c8 * 8;
    }
    // B: 512 slots (16 k-rows x 32 float4); 2/thread
    const float* bsrc[2]; int bdo[2];
#pragma unroll
    for (int j = 0; j < 2; j++) {
        int id = tid + 256 * j;
        int kq = id >> 5, nq = id & 31;
        bsrc[j] = Bbase + (size_t)kq * NOUT + nq * 4;
        bdo[j] = kq * RWB + nq * 4;
    }

    const int lane = tid & 31, wid = tid >> 5;
    const int wm = (wid >> 2) * 64, wn = (wid & 3) * 32;
    const int gid = lane >> 2, tg = lane & 3;

    float acc[4][4][4];
#pragma unroll
    for (int i = 0; i < 4; i++)
#pragma unroll
        for (int j = 0; j < 4; j++)
#pragma unroll
            for (int q = 0; q < 4; q++) acc[i][j][q] = 0.f;

    const int NC = KTOT / BK;
    const float4 zf4 = make_float4(0.f, 0.f, 0.f, 0.f);
    float4 paF[2]; uint4 paH; float4 pb[2];

    // ---- prologue: load + store stage 0 ----
    if (G1) {
#pragma unroll
        for (int j = 0; j < 2; j++) paF[j] = aok[j] ? *(const float4*)aF[j] : zf4;
    } else {
        paH = *(const uint4*)aH;
    }
#pragma unroll
    for (int j = 0; j < 2; j++) pb[j] = *(const float4*)bsrc[j];

    {
        uint32_t* a0 = &sA[0][0][0];
        uint32_t* b0 = &sB[0][0][0];
        if (G1) {
#pragma unroll
            for (int j = 0; j < 2; j++) *(uint4*)(a0 + adFo[j]) = cvt4(paF[j]);
        } else {
            __half2 h0 = *(__half2*)&paH.x, h1 = *(__half2*)&paH.y;
            __half2 h2 = *(__half2*)&paH.z, h3 = *(__half2*)&paH.w;
            float2 f0 = __half22float2(h0), f1 = __half22float2(h1);
            float2 f2 = __half22float2(h2), f3 = __half22float2(h3);
            uint4 lo, hi;
            lo.x = __float_as_uint(f0.x); lo.y = __float_as_uint(f0.y);
            lo.z = __float_as_uint(f1.x); lo.w = __float_as_uint(f1.y);
            hi.x = __float_as_uint(f2.x); hi.y = __float_as_uint(f2.y);
            hi.z = __float_as_uint(f3.x); hi.w = __float_as_uint(f3.y);
            *(uint4*)(a0 + adHo) = lo;
            *(uint4*)(a0 + adHo + 4) = hi;
        }
#pragma unroll
        for (int j = 0; j < 2; j++) *(uint4*)(b0 + bdo[j]) = cvt4(pb[j]);
    }
    __syncthreads();

#pragma unroll 1
    for (int c = 0; c < NC; c++) {
        const int cur = c & 1;
        const bool more = (c + 1 < NC);
        // prefetch next stage into regs (latency hidden under MMA section)
        if (more) {
            size_t ko = (size_t)(c + 1) * BK;
            if (G1) {
#pragma unroll
                for (int j = 0; j < 2; j++)
                    paF[j] = aok[j] ? *(const float4*)(aF[j] + ko) : zf4;
            } else {
                paH = *(const uint4*)(aH + ko);
            }
#pragma unroll
            for (int j = 0; j < 2; j++) pb[j] = *(const float4*)(bsrc[j] + ko * NOUT);
        }
        // MMA on current buffer
#pragma unroll
        for (int kk = 0; kk < 2; kk++) {
            const int kb = kk * 8;
            uint32_t bf[4][2];
#pragma unroll
            for (int nt = 0; nt < 4; nt++) {
                int n = wn + nt * 8 + gid;
                bf[nt][0] = sB[cur][kb + tg][n];
                bf[nt][1] = sB[cur][kb + 4 + tg][n];
            }
#pragma unroll
            for (int mt = 0; mt < 4; mt++) {
                uint32_t af[4];
                int r = wm + mt * 16 + gid;
                af[0] = sA[cur][r][kb + tg];
                af[1] = sA[cur][r + 8][kb + tg];
                af[2] = sA[cur][r][kb + 4 + tg];
                af[3] = sA[cur][r + 8][kb + 4 + tg];
#pragma unroll
                for (int nt = 0; nt < 4; nt++)
                    mma_tf32(acc[mt][nt], af, bf[nt]);
            }
        }
        // store next stage into the other buffer (no conflict with cur reads)
        if (more) {
            uint32_t* an = &sA[cur ^ 1][0][0];
            uint32_t* bn = &sB[cur ^ 1][0][0];
            if (G1) {
#pragma unroll
                for (int j = 0; j < 2; j++) *(uint4*)(an + adFo[j]) = cvt4(paF[j]);
            } else {
                __half2 h0 = *(__half2*)&paH.x, h1 = *(__half2*)&paH.y;
                __half2 h2 = *(__half2*)&paH.z, h3 = *(__half2*)&paH.w;
                float2 f0 = __half22float2(h0), f1 = __half22float2(h1);
                float2 f2 = __half22float2(h2), f3 = __half22float2(h3);
                uint4 lo, hi;
                lo.x = __float_as_uint(f0.x); lo.y = __float_as_uint(f0.y);
                lo.z = __float_as_uint(f1.x); lo.w = __float_as_uint(f1.y);
                hi.x = __float_as_uint(f2.x); hi.y = __float_as_uint(f2.y);
                hi.z = __float_as_uint(f3.x); hi.w = __float_as_uint(f3.y);
                *(uint4*)(an + adHo) = lo;
                *(uint4*)(an + adHo + 4) = hi;
            }
#pragma unroll
            for (int j = 0; j < 2; j++) *(uint4*)(bn + bdo[j]) = cvt4(pb[j]);
            __syncthreads();
        }
    }

    // ---------------- epilogue (C frag: c0/c1 row gid cols 2tg,2tg+1; c2/c3 row gid+8) ----------------
#pragma unroll
    for (int mt = 0; mt < 4; mt++) {
#pragma unroll
        for (int nt = 0; nt < 4; nt++) {
            int mm = wm + mt * 16 + gid;          // block-local row
            int m = row0 + mm;
            int n = n0 + wn + nt * 8 + 2 * tg;
            float b0 = bias[(size_t)e * NOUT + n];
            float b1v = bias[(size_t)e * NOUT + n + 1];
            float z00 = acc[mt][nt][0] + b0, z01 = acc[mt][nt][1] + b1v;
            float z10 = acc[mt][nt][2] + b0, z11 = acc[mt][nt][3] + b1v;
            if (G1) {
                z00 = fmaxf(z00, 0.f); z01 = fmaxf(z01, 0.f);
                z10 = fmaxf(z10, 0.f); z11 = fmaxf(z11, 0.f);
                if (mm < valid)
                    *(uint32_t*)(g_hf16 + (size_t)m * NOUT + n) = f2h2(z00, z01);
                if (mm + 8 < valid)
                    *(uint32_t*)(g_hf16 + (size_t)(m + 8) * NOUT + n) = f2h2(z10, z11);
            } else {
                if (mm < valid)
                    *(float2*)(g_y + (size_t)m * NOUT + n) = make_float2(z00, z01);
                if (mm + 8 < valid)
                    *(float2*)(g_y + (size_t)(m + 8) * NOUT + n) = make_float2(z10, z11);
            }
        }
    }
}

// ---------------- combine (also resets counts for the next launch/replay) ----------------
__global__ void combine_kernel(float* __restrict__ out) {
    int n = blockIdx.x;
    int r0 = g_row_of_pair[2 * n];
    int r1 = g_row_of_pair[2 * n + 1];
    float w0 = g_top_w[2 * n];
    float w1 = g_top_w[2 * n + 1];
    const float4* y0 = (const float4*)&g_y[(size_t)r0 * OO];
    const float4* y1 = (const float4*)&g_y[(size_t)r1 * OO];
    float4* o = (float4*)&out[(size_t)n * OO];
    int t = threadIdx.x;
    float4 a = y0[t], b = y1[t];
    float4 r;
    r.x = w0 * a.x + w1 * b.x;
    r.y = w0 * a.y + w1 * b.y;
    r.z = w0 * a.z + w1 * b.z;
    r.w = w0 * a.w + w1 * b.w;
    o[t] = r;
    if (n == 0 && t < EE) g_counts[t] = 0;   // .bss starts zero; invariant per call
}

// ---------------- launch ----------------
extern "C" void kernel_launch(void* const* d_in, const int* in_sizes, int n_in,
                              void* d_out, int out_size) {
    const float* x  = (const float*)d_in[0];
    const float* Wg = (const float*)d_in[1];
    const float* bg = (const float*)d_in[2];
    const float* W1 = (const float*)d_in[3];
    const float* b1 = (const float*)d_in[4];
    const float* W2 = (const float*)d_in[5];
    const float* b2 = (const float*)d_in[6];
    float* out = (float*)d_out;

    router_kernel<<<NTOK / 8, 256>>>(x, Wg, bg);
    scan_kernel<<<1, 1>>>();
    scatter_kernel<<<NPAIR / 256, 256>>>();

    moe_gemm<DD, HH, true><<<dim3(HH / BN, ROWS_CAP / BM), 256>>>(x, W1, b1);
    moe_gemm<HH, OO, false><<<dim3(OO / BN, ROWS_CAP / BM), 256>>>(x, W2, b2);

    combine_kernel<<<NTOK, 256>>>(out);
}

// round 16
// speedup vs baseline: 1.2819x; 1.2819x over previous
#include <cuda_runtime.h>
#include <cuda_fp16.h>
#include <cstdint>

// ---------------- problem constants ----------------
#define DD   1024
#define EE   8
#define HH   4096
#define OO   1024
#define NTOK 4096
#define NPAIR (NTOK * 2)
#define ROWS_CAP (NPAIR + EE * 128)   // 9216

// ---------------- GEMM tile config ----------------
#define BM 64        // small M tile -> 32 accs/thread -> 2 CTAs/SM
#define BN 128
#define BK 32
#define RWA 36       // A smem pitch (u32): frag loads conflict-free
#define RWB 136      // B smem pitch (u32): 136%32==8 -> frag loads conflict-free

// ---------------- asm helpers ----------------
__device__ __forceinline__ void mma_tf32(float* c, const uint32_t* a, const uint32_t* b) {
    asm volatile("mma.sync.aligned.m16n8k8.row.col.f32.tf32.tf32.f32 "
                 "{%0,%1,%2,%3}, {%4,%5,%6,%7}, {%8,%9}, {%0,%1,%2,%3};"
                 : "+f"(c[0]), "+f"(c[1]), "+f"(c[2]), "+f"(c[3])
                 : "r"(a[0]), "r"(a[1]), "r"(a[2]), "r"(a[3]), "r"(b[0]), "r"(b[1]));
}
__device__ __forceinline__ uint32_t f2tf32(float v) {
    uint32_t r;
    asm("cvt.rna.tf32.f32 %0, %1;" : "=r"(r) : "f"(v));
    return r;
}
__device__ __forceinline__ uint4 cvt4(float4 v) {
    uint4 o;
    o.x = f2tf32(v.x); o.y = f2tf32(v.y);
    o.z = f2tf32(v.z); o.w = f2tf32(v.w);
    return o;
}
__device__ __forceinline__ uint32_t f2h2(float lo, float hi) {
    __half2 h = __floats2half2_rn(lo, hi);
    return *(uint32_t*)&h;
}

// ---------------- scratch (static device globals; device-code access ONLY) ----------------
__device__ int   g_counts[EE];
__device__ int   g_cursor[EE];
__device__ int   g_off[EE + 1];
__device__ int   g_top_idx[NPAIR];
__device__ float g_top_w[NPAIR];
__device__ int   g_row_token[ROWS_CAP];
__device__ int   g_row_of_pair[NPAIR];
__device__ __align__(16) __half g_hf16[(size_t)ROWS_CAP * HH];   // hidden, fp16
__device__ __align__(16) float  g_y[(size_t)ROWS_CAP * OO];

// ---------------- small kernels ----------------
__global__ void router_kernel(const float* __restrict__ x,
                              const float* __restrict__ Wg,
                              const float* __restrict__ bg) {
    __shared__ float sWg[DD * EE];
    int tid = threadIdx.x;
    for (int i = tid * 4; i < DD * EE; i += blockDim.x * 4)
        *(float4*)&sWg[i] = *(const float4*)&Wg[i];
    __syncthreads();

    int warp = tid >> 5, lane = tid & 31;
    int n = blockIdx.x * 8 + warp;
    const float* xr = x + (size_t)n * DD;

    float acc[EE];
#pragma unroll
    for (int e = 0; e < EE; e++) acc[e] = 0.f;
    for (int d = lane; d < DD; d += 32) {
        float xv = xr[d];
#pragma unroll
        for (int e = 0; e < EE; e++) acc[e] += xv * sWg[d * EE + e];
    }
#pragma unroll
    for (int e = 0; e < EE; e++)
#pragma unroll
        for (int s = 16; s; s >>= 1) acc[e] += __shfl_xor_sync(0xffffffffu, acc[e], s);

    if (lane == 0) {
        float m = -1e30f;
#pragma unroll
        for (int e = 0; e < EE; e++) { acc[e] += bg[e]; m = fmaxf(m, acc[e]); }
        float s = 0.f;
#pragma unroll
        for (int e = 0; e < EE; e++) { acc[e] = __expf(acc[e] - m); s += acc[e]; }
        float inv = 1.f / s;
        int i0 = 0; float p0 = acc[0];
#pragma unroll
        for (int e = 1; e < EE; e++) if (acc[e] > p0) { p0 = acc[e]; i0 = e; }
        int i1 = -1; float p1 = -1.f;
#pragma unroll
        for (int e = 0; e < EE; e++) if (e != i0 && acc[e] > p1) { p1 = acc[e]; i1 = e; }

        g_top_idx[2 * n]     = i0; g_top_w[2 * n]     = p0 * inv;
        g_top_idx[2 * n + 1] = i1; g_top_w[2 * n + 1] = p1 * inv;
        atomicAdd(&g_counts[i0], 1);
        atomicAdd(&g_counts[i1], 1);
    }
}

__global__ void scan_kernel() {
    int off = 0;
    for (int e = 0; e < EE; e++) {
        g_off[e] = off;
        g_cursor[e] = off;
        off += (g_counts[e] + 127) & ~127;   // keep 128-aligned (multiple of BM=64)
    }
    g_off[EE] = off;
}

__global__ void scatter_kernel() {
    int p = blockIdx.x * blockDim.x + threadIdx.x;
    if (p >= NPAIR) return;
    int e = g_top_idx[p];
    int pos = atomicAdd(&g_cursor[e], 1);
    g_row_token[pos] = p >> 1;
    g_row_of_pair[p] = pos;
}

// ---------------- TF32 grouped GEMM: 64x128 tile, 2 CTAs/SM ----------------
// Same proven single-buffer BK=32 loop as the 1087us kernel; the second
// co-resident CTA (reg-capped via launch_bounds) covers barrier windows.
template <int KTOT, int NOUTT, bool G1>
__global__ __launch_bounds__(256, 2) void moe_gemm(const float* __restrict__ xArg,
                                                   const float* __restrict__ Barg,
                                                   const float* __restrict__ bias) {
    const int NOUT = NOUTT;

    __shared__ __align__(16) uint32_t sA[BM][RWA];     // [m][k] fp32(tf32)
    __shared__ __align__(16) uint32_t sB[BK][RWB];     // [k][n] fp32(tf32)
    __shared__ int stok[BM];

    const int tid = threadIdx.x;
    const int row0 = blockIdx.y * BM;
    if (row0 >= g_off[EE]) return;
    int e = 0;
#pragma unroll
    for (int i = 1; i < EE; i++) if (row0 >= g_off[i]) e = i;
    const int valid = g_off[e] + g_counts[e] - row0;
    const int n0 = blockIdx.x * BN;
    const float* __restrict__ Bbase = Barg + (size_t)e * KTOT * NOUT + n0;

    if (G1) {
        if (tid < BM) stok[tid] = (tid < valid) ? g_row_token[row0 + tid] : -1;
        __syncthreads();
    }

    // ---- loader slots (per K-stage of 32) ----
    // G1 A: 512 slots (64 rows x 8 float4); 2/thread
    const float* aF[2]; int adFo[2]; bool aok[2];
    // G2 A: 256 slots (64 rows x 4 eight-half chunks); 1/thread
    const __half* aH = nullptr; int adHo = 0;
    if (G1) {
#pragma unroll
        for (int j = 0; j < 2; j++) {
            int id = tid + 256 * j;
            int r = id >> 3, ch = id & 7;
            int tk = stok[r];
            aok[j] = (tk >= 0);
            long ar = aok[j] ? tk : 0;
            aF[j] = xArg + (size_t)ar * KTOT + ch * 4;
            adFo[j] = r * RWA + ch * 4;
        }
    } else {
        int r = tid >> 2, c8 = tid & 3;
        aH = g_hf16 + (size_t)(row0 + r) * KTOT + c8 * 8;
        adHo = r * RWA + c8 * 8;
    }
    // B: 1024 slots (32 k-rows x 32 float4); 4/thread
    const float* bsrc[4]; int bdo[4];
#pragma unroll
    for (int j = 0; j < 4; j++) {
        int id = tid + 256 * j;
        int kq = id >> 5, nq = id & 31;
        bsrc[j] = Bbase + (size_t)kq * NOUT + nq * 4;
        bdo[j] = kq * RWB + nq * 4;
    }

    const int lane = tid & 31, wid = tid >> 5;
    const int wm = (wid >> 2) * 32, wn = (wid & 3) * 32;   // 2x4 warp grid, 32x32 tiles
    const int gid = lane >> 2, tg = lane & 3;

    float acc[2][4][4];
#pragma unroll
    for (int i = 0; i < 2; i++)
#pragma unroll
        for (int j = 0; j < 4; j++)
#pragma unroll
            for (int q = 0; q < 4; q++) acc[i][j][q] = 0.f;

    const int NC = KTOT / BK;
    const float4 zf4 = make_float4(0.f, 0.f, 0.f, 0.f);
    float4 paF[2]; uint4 paH; float4 pb[4];
    if (G1) {
#pragma unroll
        for (int j = 0; j < 2; j++) paF[j] = aok[j] ? *(const float4*)aF[j] : zf4;
    } else {
        paH = *(const uint4*)aH;
    }
#pragma unroll
    for (int j = 0; j < 4; j++) pb[j] = *(const float4*)bsrc[j];

    uint32_t* a0 = &sA[0][0];
    uint32_t* b0 = &sB[0][0];

#pragma unroll 1
    for (int c = 0; c < NC; c++) {
        __syncthreads();   // previous iter's smem reads done before overwrite
        if (G1) {
#pragma unroll
            for (int j = 0; j < 2; j++) *(uint4*)(a0 + adFo[j]) = cvt4(paF[j]);
        } else {
            __half2 h0 = *(__half2*)&paH.x, h1 = *(__half2*)&paH.y;
            __half2 h2 = *(__half2*)&paH.z, h3 = *(__half2*)&paH.w;
            float2 f0 = __half22float2(h0), f1 = __half22float2(h1);
            float2 f2 = __half22float2(h2), f3 = __half22float2(h3);
            uint4 lo, hi;
            lo.x = __float_as_uint(f0.x); lo.y = __float_as_uint(f0.y);
            lo.z = __float_as_uint(f1.x); lo.w = __float_as_uint(f1.y);
            hi.x = __float_as_uint(f2.x); hi.y = __float_as_uint(f2.y);
            hi.z = __float_as_uint(f3.x); hi.w = __float_as_uint(f3.y);
            *(uint4*)(a0 + adHo) = lo;
            *(uint4*)(a0 + adHo + 4) = hi;
        }
#pragma unroll
        for (int j = 0; j < 4; j++) *(uint4*)(b0 + bdo[j]) = cvt4(pb[j]);
        __syncthreads();
        if (c + 1 < NC) {  // prefetch next K-slab into regs (hidden by MMAs)
            size_t ko = (size_t)(c + 1) * BK;
            if (G1) {
#pragma unroll
                for (int j = 0; j < 2; j++)
                    paF[j] = aok[j] ? *(const float4*)(aF[j] + ko) : zf4;
            } else {
                paH = *(const uint4*)(aH + ko);
            }
#pragma unroll
            for (int j = 0; j < 4; j++) pb[j] = *(const float4*)(bsrc[j] + ko * NOUT);
        }
#pragma unroll
        for (int kk = 0; kk < 4; kk++) {
            const int kb = kk * 8;   // 8 fp32 = K8 per mma step
            uint32_t bf[4][2];
#pragma unroll
            for (int nt = 0; nt < 4; nt++) {
                int n = wn + nt * 8 + gid;
                bf[nt][0] = sB[kb + tg][n];
                bf[nt][1] = sB[kb + 4 + tg][n];
            }
#pragma unroll
            for (int mt = 0; mt < 2; mt++) {
                uint32_t af[4];
                int r = wm + mt * 16 + gid;
                af[0] = sA[r][kb + tg];
                af[1] = sA[r + 8][kb + tg];
                af[2] = sA[r][kb + 4 + tg];
                af[3] = sA[r + 8][kb + 4 + tg];
#pragma unroll
                for (int nt = 0; nt < 4; nt++)
                    mma_tf32(acc[mt][nt], af, bf[nt]);
            }
        }
    }

    // ---------------- epilogue (C frag: c0/c1 row gid cols 2tg,2tg+1; c2/c3 row gid+8) ----------------
#pragma unroll
    for (int mt = 0; mt < 2; mt++) {
#pragma unroll
        for (int nt = 0; nt < 4; nt++) {
            int mm = wm + mt * 16 + gid;          // block-local row
            int m = row0 + mm;
            int n = n0 + wn + nt * 8 + 2 * tg;
            float b0 = bias[(size_t)e * NOUT + n];
            float b1v = bias[(size_t)e * NOUT + n + 1];
            float z00 = acc[mt][nt][0] + b0, z01 = acc[mt][nt][1] + b1v;
            float z10 = acc[mt][nt][2] + b0, z11 = acc[mt][nt][3] + b1v;
            if (G1) {
                z00 = fmaxf(z00, 0.f); z01 = fmaxf(z01, 0.f);
                z10 = fmaxf(z10, 0.f); z11 = fmaxf(z11, 0.f);
                if (mm < valid)
                    *(uint32_t*)(g_hf16 + (size_t)m * NOUT + n) = f2h2(z00, z01);
                if (mm + 8 < valid)
                    *(uint32_t*)(g_hf16 + (size_t)(m + 8) * NOUT + n) = f2h2(z10, z11);
            } else {
                if (mm < valid)
                    *(float2*)(g_y + (size_t)m * NOUT + n) = make_float2(z00, z01);
                if (mm + 8 < valid)
                    *(float2*)(g_y + (size_t)(m + 8) * NOUT + n) = make_float2(z10, z11);
            }
        }
    }
}

// ---------------- combine (also resets counts for the next launch/replay) ----------------
__global__ void combine_kernel(float* __restrict__ out) {
    int n = blockIdx.x;
    int r0 = g_row_of_pair[2 * n];
    int r1 = g_row_of_pair[2 * n + 1];
    float w0 = g_top_w[2 * n];
    float w1 = g_top_w[2 * n + 1];
    const float4* y0 = (const float4*)&g_y[(size_t)r0 * OO];
    const float4* y1 = (const float4*)&g_y[(size_t)r1 * OO];
    float4* o = (float4*)&out[(size_t)n * OO];
    int t = threadIdx.x;
    float4 a = y0[t], b = y1[t];
    float4 r;
    r.x = w0 * a.x + w1 * b.x;
    r.y = w0 * a.y + w1 * b.y;
    r.z = w0 * a.z + w1 * b.z;
    r.w = w0 * a.w + w1 * b.w;
    o[t] = r;
    if (n == 0 && t < EE) g_counts[t] = 0;   // .bss starts zero; invariant per call
}

// ---------------- launch ----------------
extern "C" void kernel_launch(void* const* d_in, const int* in_sizes, int n_in,
                              void* d_out, int out_size) {
    const float* x  = (const float*)d_in[0];
    const float* Wg = (const float*)d_in[1];
    const float* bg = (const float*)d_in[2];
    const float* W1 = (const float*)d_in[3];
    const float* b1 = (const float*)d_in[4];
    const float* W2 = (const float*)d_in[5];
    const float* b2 = (const float*)d_in[6];
    float* out = (float*)d_out;

    router_kernel<<<NTOK / 8, 256>>>(x, Wg, bg);
    scan_kernel<<<1, 1>>>();
    scatter_kernel<<<NPAIR / 256, 256>>>();

    moe_gemm<DD, HH, true><<<dim3(HH / BN, ROWS_CAP / BM), 256>>>(x, W1, b1);
    moe_gemm<HH, OO, false><<<dim3(OO / BN, ROWS_CAP / BM), 256>>>(x, W2, b2);

    combine_kernel<<<NTOK, 256>>>(out);
}